// round 17
// baseline (speedup 1.0000x reference)
#include <cuda_runtime.h>
#include <cuda_fp16.h>
#include <cstdint>

// ---------------------------------------------------------------------------
// Problem constants
// ---------------------------------------------------------------------------
#define N_PTS   524288
#define Dd      64
#define Hh      256
#define Ww      256
#define MAPSZ   (2*Dd*Hh*Ww)     // 8,388,608
#define THREADS 256
#define PTS_BLK 64               // 4 point-groups x 16, 2 warps per group
#define NBLK    (N_PTS/PTS_BLK)  // 8192
#define CIN     64
#define COUT    128

#define A_PITCH 144              // 64 halfs (128B) + 16B pad
#define WSLICE  (16*A_PITCH)     // per-warp A slice: 2304 B
#define NBUF    4                // per-warp pipeline depth (distance 3)

// smem: bias(512) @0, A slices @1024: 8 warps x 4 bufs x 2304 = 73728
#define OFF_BIAS   0
#define OFF_A      1024
#define SMEM_TOTAL (1024 + 8*NBUF*WSLICE)    // 74752 -> 3 CTAs/SM = 224256 B

__device__ int    g_map[MAPSZ];                  // 0 = empty, else pid+1
__device__ __half g_feat[(size_t)N_PTS*CIN];     // fp16 [x||h] features
__device__ uint4  g_wfrag[27*4*8*32];            // fragment-ordered weights

// {dz, dy, dx, dk = dz*65536 + dy*256 + dx}
__constant__ int4 c_off[27] = {
    {-1,-1,-1,-65793},{-1,-1,0,-65792},{-1,-1,1,-65791},
    {-1, 0,-1,-65537},{-1, 0,0,-65536},{-1, 0,1,-65535},
    {-1, 1,-1,-65281},{-1, 1,0,-65280},{-1, 1,1,-65279},
    { 0,-1,-1,  -257},{ 0,-1,0,  -256},{ 0,-1,1,  -255},
    { 0, 0,-1,    -1},{ 0, 0,0,     0},{ 0, 0,1,     1},
    { 0, 1,-1,   255},{ 0, 1,0,   256},{ 0, 1,1,   257},
    { 1,-1,-1, 65279},{ 1,-1,0, 65280},{ 1,-1,1, 65281},
    { 1, 0,-1, 65535},{ 1, 0,0, 65536},{ 1, 0,1, 65537},
    { 1, 1,-1, 65791},{ 1, 1,0, 65792},{ 1, 1,1, 65793}
};

// ---------------------------------------------------------------------------
// helpers
// ---------------------------------------------------------------------------
__device__ __forceinline__ uint32_t smem_u32(const void* p) {
    uint32_t a;
    asm("{ .reg .u64 t; cvta.to.shared.u64 t, %1; cvt.u32.u64 %0, t; }"
        : "=r"(a) : "l"(p));
    return a;
}
__device__ __forceinline__ uint32_t h2_bits(__half2 h) {
    return *reinterpret_cast<uint32_t*>(&h);
}
__device__ __forceinline__ void ldsm4(uint32_t* r, uint32_t a) {
    asm volatile("ldmatrix.sync.aligned.m8n8.x4.shared.b16 {%0,%1,%2,%3},[%4];"
                 : "=r"(r[0]), "=r"(r[1]), "=r"(r[2]), "=r"(r[3]) : "r"(a));
}
__device__ __forceinline__ void mma16816(float* d, const uint32_t* a,
                                         const uint32_t* b) {
    asm volatile("mma.sync.aligned.m16n8k16.row.col.f32.f16.f16.f32 "
                 "{%0,%1,%2,%3},{%4,%5,%6,%7},{%8,%9},{%0,%1,%2,%3};"
                 : "+f"(d[0]), "+f"(d[1]), "+f"(d[2]), "+f"(d[3])
                 : "r"(a[0]), "r"(a[1]), "r"(a[2]), "r"(a[3]),
                   "r"(b[0]), "r"(b[1]));
}
__device__ __forceinline__ void cpa16(uint32_t d, const void* s, int sz) {
    asm volatile("cp.async.cg.shared.global [%0], [%1], 16, %2;"
                 :: "r"(d), "l"(s), "r"(sz));
}
#define CPA_COMMIT() asm volatile("cp.async.commit_group;" ::: "memory")
#define CPA_WAIT2()  asm volatile("cp.async.wait_group 2;"  ::: "memory")
#define CPA_WAIT1()  asm volatile("cp.async.wait_group 1;"  ::: "memory")
#define CPA_WAIT0()  asm volatile("cp.async.wait_group 0;"  ::: "memory")

__device__ __forceinline__ float sigm_f(float x) { return 1.0f/(1.0f+__expf(-x)); }
__device__ __forceinline__ float tanh_f(float x) {
    float e = __expf(2.0f*x); return 1.0f - 2.0f/(e + 1.0f);
}

// ---------------------------------------------------------------------------
// Pre-pass: fp16 features, fragment-ordered weights, map scatter (unchanged)
// ---------------------------------------------------------------------------
__global__ __launch_bounds__(512) void k_pre(
    const float* __restrict__ xf, const float* __restrict__ hf,
    const float* __restrict__ wt, const int* __restrict__ coors)
{
    int i = blockIdx.x * blockDim.x + threadIdx.x;
    {
        int pt = i >> 3, seg = i & 7;
        const float* bp = (seg < 4) ? xf + (size_t)pt*32 + seg*8
                                    : hf + (size_t)pt*32 + (seg - 4)*8;
        float4 v0 = reinterpret_cast<const float4*>(bp)[0];
        float4 v1 = reinterpret_cast<const float4*>(bp)[1];
        uint4 pk;
        pk.x = h2_bits(__floats2half2_rn(v0.x, v0.y));
        pk.y = h2_bits(__floats2half2_rn(v0.z, v0.w));
        pk.z = h2_bits(__floats2half2_rn(v1.x, v1.y));
        pk.w = h2_bits(__floats2half2_rn(v1.z, v1.w));
        reinterpret_cast<uint4*>(g_feat)[i] = pk;
    }
    if (i < 27*1024) {              // fragment-ordered weight build
        int k    = i >> 10;
        int kk   = (i >> 8) & 3;
        int np   = (i >> 5) & 7;
        int lane = i & 31;
        const float* wk = wt + k*8192;
        uint32_t r[4];
        #pragma unroll
        for (int rr = 0; rr < 4; rr++) {
            int n = np*16 + (rr >> 1)*8 + (lane >> 2);
            int blk = n >> 6, g = (n >> 4) & 3, chlo = n & 15;
            int orig = g*32 + blk*16 + chlo;
            int j0 = kk*16 + (rr & 1)*8 + 2*(lane & 3);
            r[rr] = h2_bits(__floats2half2_rn(wk[j0*128 + orig],
                                              wk[(j0 + 1)*128 + orig]));
        }
        g_wfrag[i] = make_uint4(r[0], r[1], r[2], r[3]);
    }
    if (i < N_PTS) {
        int4 c = reinterpret_cast<const int4*>(coors)[i];
        g_map[((c.x*Dd + c.y)*Hh + c.z)*Ww + c.w] = i + 1;
    }
}

// ---------------------------------------------------------------------------
// Main kernel: 64 pts/block, 8 warps; each warp = m16 x n64 tile (2 warps per
// point-group, one per n64 half; gate permutation keeps epilogue thread-local).
// acc = 32 regs -> 3 CTAs/SM (24 warps). Warp-private A slices + per-warp
// cp.async pipeline (distance 3), no block barrier in the main loop; B frags
// via LDG.128 (L2-hot); constant offset table; software-pipelined LDSM.
// ---------------------------------------------------------------------------
__global__ __launch_bounds__(THREADS, 3) void k_main(
    const float* __restrict__ cf, const float* __restrict__ bias,
    const int* __restrict__ coors, float* __restrict__ out)
{
    extern __shared__ __align__(16) char smem[];
    const uint32_t sb = smem_u32(smem);
    const int tid = threadIdx.x, w = tid >> 5, lane = tid & 31;
    const int gid = lane >> 2, tig = lane & 3;
    const int pg = w >> 1, h = w & 1;        // point-group, n64 half
    const int pblk = blockIdx.x * PTS_BLK;

    float* s_bias = reinterpret_cast<float*>(smem + OFF_BIAS);
    if (tid < 128) {
        int gate = tid >> 5, ch = tid & 31;
        s_bias[(ch >> 4)*64 + gate*16 + (ch & 15)] = bias[tid];
    }
    __syncthreads();                      // only block barrier in the kernel

    // this lane gathers half of row (lane>>1) of my warp's 16-row tile
    const int row16 = lane >> 1;
    const int ghalf = lane & 1;
    const int grow  = pg*16 + row16;
    int4 cc = reinterpret_cast<const int4*>(coors)[pblk + grow];
    const int4 pc = make_int4(cc.y, cc.z, cc.w,
                              ((cc.x*Dd + cc.y)*Hh + cc.z)*Ww + cc.w);

    const uint32_t aslice = sb + OFF_A + w*NBUF*WSLICE;
    const uint32_t adst0  = aslice + row16*A_PITCH + ghalf*64;  // + buf*WSLICE
    const uint32_t abase0 = aslice + (lane & 15)*A_PITCH + (lane >> 4)*16;

    float acc[8][4];
    #pragma unroll
    for (int t = 0; t < 8; t++)
        #pragma unroll
        for (int q = 0; q < 4; q++) acc[t][q] = 0.f;

    auto map_probe = [&](int kn) -> int {
        const int4 o = c_off[kn];
        int nz = pc.x + o.x, ny = pc.y + o.y, nx = pc.z + o.z;
        if ((unsigned)nz < Dd && (unsigned)ny < Hh && (unsigned)nx < Ww)
            return g_map[pc.w + o.w] - 1;
        return -1;
    };

    // gather my warp's 16 A rows for offset kn into private buffer; ret flag
    auto issue = [&](int kn, int nid) -> int {
        unsigned bal = __ballot_sync(0xffffffffu, nid >= 0);
        if (bal) {
            const char* src = reinterpret_cast<const char*>(
                g_feat + (size_t)max(nid, 0)*64) + ghalf*64;
            const int sz = (nid >= 0) ? 16 : 0;
            uint32_t adst = adst0 + (kn & (NBUF-1))*WSLICE;
            #pragma unroll
            for (int c = 0; c < 4; c++) cpa16(adst + c*16, src + c*16, sz);
        }
        return bal != 0;
    };

    // prologue: three offsets in flight (per-warp pipeline)
    int f0 = issue(0, map_probe(0)); CPA_COMMIT();
    int f1 = issue(1, map_probe(1)); CPA_COMMIT();
    int f2 = issue(2, map_probe(2)); CPA_COMMIT();
    int nid_pend = map_probe(3);
    int f3 = 0;

    // my warp's B frags: np range h*4 .. h*4+3
    const uint4* wfk = g_wfrag + h*4*32 + lane;      // += 1024 per offset

    for (int k = 0; k < 27; k++) {
        const int buf = k & (NBUF-1);
        if      (k < 25)  { CPA_WAIT2(); }
        else if (k == 25) { CPA_WAIT1(); }
        else              { CPA_WAIT0(); }
        __syncwarp();                      // my warp's copies for k visible
        if (k < 24) {
            f3 = issue(k + 3, nid_pend);
            CPA_COMMIT();
            if (k < 23) nid_pend = map_probe(k + 4);   // hidden by compute(k)
        }

        if (f0) {
            const uint32_t abase = abase0 + buf*WSLICE;
            uint32_t a0[4], a1[4];
            ldsm4(a0, abase);                       // A frag for kk=0
            #pragma unroll
            for (int kk = 0; kk < 4; kk++) {
                uint32_t* acur = (kk & 1) ? a1 : a0;
                uint32_t* anxt = (kk & 1) ? a0 : a1;
                if (kk < 3) ldsm4(anxt, abase + (kk + 1)*32);  // prefetch
                uint4 b[4];
                #pragma unroll
                for (int j = 0; j < 4; j++)
                    b[j] = wfk[kk*256 + j*32];
                #pragma unroll
                for (int j = 0; j < 4; j++) {
                    mma16816(acc[2*j],     acur, &b[j].x);
                    mma16816(acc[2*j + 1], acur, &b[j].z);
                }
            }
        }
        f0 = f1; f1 = f2; f2 = f3;
        wfk += 1024;
    }

    // ---- fused LSTM epilogue (thread-local via gate permutation) ----
    // warp covers channels h*16 .. h*16+15 (all 4 gates) for its 16 rows
    float* outh = out;
    float* outc = out + (size_t)N_PTS * 32;
    #pragma unroll
    for (int rh = 0; rh < 2; rh++) {
        const int row = pblk + pg*16 + rh*8 + gid;
        #pragma unroll
        for (int p = 0; p < 2; p++) {
            const int ch = h*16 + p*8 + 2*tig;
            const int bb = h*64 + p*8 + 2*tig;
            float2 bi  = *reinterpret_cast<float2*>(&s_bias[bb]);
            float2 bff = *reinterpret_cast<float2*>(&s_bias[bb + 16]);
            float2 bo  = *reinterpret_cast<float2*>(&s_bias[bb + 32]);
            float2 bg  = *reinterpret_cast<float2*>(&s_bias[bb + 48]);
            float2 cp  = *reinterpret_cast<const float2*>(
                             &cf[(size_t)row*32 + ch]);
            float hn[2], cn[2];
            #pragma unroll
            for (int q = 0; q < 2; q++) {
                float iv = sigm_f(acc[0 + p][rh*2 + q] + (q ? bi.y  : bi.x));
                float fv = sigm_f(acc[2 + p][rh*2 + q] + (q ? bff.y : bff.x));
                float ov = sigm_f(acc[4 + p][rh*2 + q] + (q ? bo.y  : bo.x));
                float gt = tanh_f(acc[6 + p][rh*2 + q] + (q ? bg.y  : bg.x));
                float cpv = q ? cp.y : cp.x;
                cn[q] = fv * cpv + iv * gt;
                hn[q] = ov * tanh_f(cn[q]);
            }
            *reinterpret_cast<float2*>(&outh[(size_t)row*32 + ch]) =
                make_float2(hn[0], hn[1]);
            *reinterpret_cast<float2*>(&outc[(size_t)row*32 + ch]) =
                make_float2(cn[0], cn[1]);
        }
    }
}

// ---------------------------------------------------------------------------
// Launch
// ---------------------------------------------------------------------------
extern "C" void kernel_launch(void* const* d_in, const int* in_sizes, int n_in,
                              void* d_out, int out_size)
{
    (void)in_sizes; (void)n_in; (void)out_size;
    const float* xf    = (const float*)d_in[0];
    const float* hf    = (const float*)d_in[1];
    const float* cf    = (const float*)d_in[2];
    const float* wt    = (const float*)d_in[3];
    const float* bs    = (const float*)d_in[4];
    const int*   coors = (const int*)  d_in[5];

    cudaFuncSetAttribute(k_main, cudaFuncAttributeMaxDynamicSharedMemorySize,
                         SMEM_TOTAL);

    k_pre  <<<8192, 512>>>(xf, hf, wt, coors);
    k_main <<<NBLK, THREADS, SMEM_TOTAL>>>(cf, bs, coors, (float*)d_out);
}